// round 1
// baseline (speedup 1.0000x reference)
#include <cuda_runtime.h>
#include <cstdint>

#define BB 64
#define SS 400
#define HH 512
#define EE 300
#define VOCAB 50000
#define KOUT 1024   // 2H
#define KG   1324   // E + H + H
#define GR   2048   // 4H

#define OUT_H_OFF (BB * VOCAB)
#define OUT_C_OFF (BB * VOCAB + BB * HH)

// ---------------- scratch (device globals; no allocations allowed) ----------
__device__ float g_attw[BB * SS];
__device__ float g_xeT[EE * BB];     // [e][b]
__device__ float g_ctxT[HH * BB];    // [h][b]
__device__ float g_hprevT[HH * BB];  // [h][b]
__device__ float g_hnewT[HH * BB];   // [h][b]
__device__ float g_gates[BB * GR];   // [b][r]
__device__ float g_pgen[BB];

// ---------------- helpers ----------------------------------------------------
typedef unsigned long long ull;

__device__ __forceinline__ ull pack2(float lo, float hi) {
    ull r; asm("mov.b64 %0,{%1,%2};" : "=l"(r) : "f"(lo), "f"(hi)); return r;
}
__device__ __forceinline__ void unpack2(ull v, float& lo, float& hi) {
    asm("mov.b64 {%0,%1},%2;" : "=f"(lo), "=f"(hi) : "l"(v));
}
__device__ __forceinline__ void fma2(ull& d, ull a, ull b) {
    asm("fma.rn.f32x2 %0,%1,%2,%3;" : "=l"(d) : "l"(a), "l"(b), "l"(d));
}

__device__ __forceinline__ float fast_tanh(float x) {
    // tanh(x) = 1 - 2/(exp(2x)+1); exp overflow/underflow -> exact +-1
    float e = __expf(x + x);
    return 1.f - __fdividef(2.f, e + 1.f);
}
__device__ __forceinline__ float fast_sigm(float x) {
    return __fdividef(1.f, 1.f + __expf(-x));
}

// ---------------- embedding gather (transposed) ------------------------------
__global__ void k_embed(const int* __restrict__ x, const float* __restrict__ emb) {
    int t = threadIdx.x;
    int b = t & 63;
    int e = blockIdx.x * 4 + (t >> 6);
    if (e < EE) g_xeT[e * BB + b] = emb[(size_t)x[b] * EE + e];
}

// ---------------- attention: scores -> softmax -> ctx ------------------------
__global__ void k_attn(const float* __restrict__ enc, const float* __restrict__ h0,
                       const float* __restrict__ Vw, const float* __restrict__ Vb) {
    __shared__ float sh_h[HH];
    __shared__ float sh_vw[HH];
    __shared__ float sh_sc[SS];
    __shared__ float sh_red[8];

    int b = blockIdx.x;
    int t = threadIdx.x;
    int lane = t & 31, w = t >> 5;

    for (int i = t; i < HH; i += 256) {
        float hv = h0[b * HH + i];
        sh_h[i] = hv;
        g_hprevT[i * BB + b] = hv;
        sh_vw[i] = Vw[i];
    }
    __syncthreads();

    const float* encb = enc + (size_t)b * (SS * HH);
    float vb = Vb[0];

    // phase A: scores (warp per s)
    for (int s = w; s < SS; s += 8) {
        const float* row = encb + s * HH;
        float p = 0.f;
#pragma unroll
        for (int j = 0; j < 16; j++) {
            int h = j * 32 + lane;
            p += fast_tanh(row[h] + sh_h[h]) * sh_vw[h];
        }
#pragma unroll
        for (int o = 16; o; o >>= 1) p += __shfl_xor_sync(~0u, p, o);
        if (lane == 0) sh_sc[s] = p + vb;
    }
    __syncthreads();

    // phase B: softmax over S
    float m = -3.4e38f;
    for (int s = t; s < SS; s += 256) m = fmaxf(m, sh_sc[s]);
#pragma unroll
    for (int o = 16; o; o >>= 1) m = fmaxf(m, __shfl_xor_sync(~0u, m, o));
    if (lane == 0) sh_red[w] = m;
    __syncthreads();
    m = sh_red[0];
#pragma unroll
    for (int i = 1; i < 8; i++) m = fmaxf(m, sh_red[i]);
    __syncthreads();

    float ssum = 0.f;
    for (int s = t; s < SS; s += 256) {
        float e = __expf(sh_sc[s] - m);
        sh_sc[s] = e;
        ssum += e;
    }
#pragma unroll
    for (int o = 16; o; o >>= 1) ssum += __shfl_xor_sync(~0u, ssum, o);
    if (lane == 0) sh_red[w] = ssum;
    __syncthreads();
    ssum = 0.f;
#pragma unroll
    for (int i = 0; i < 8; i++) ssum += sh_red[i];
    float inv = 1.f / ssum;

    for (int s = t; s < SS; s += 256) {
        float wv = sh_sc[s] * inv;
        sh_sc[s] = wv;
        g_attw[b * SS + s] = wv;
    }
    __syncthreads();

    // phase C: ctx[h] = sum_s w[s] * enc[b,s,h]; thread handles h=t, t+256
    float a0 = 0.f, a1 = 0.f;
#pragma unroll 4
    for (int s = 0; s < SS; s++) {
        float wv = sh_sc[s];
        a0 = fmaf(wv, encb[s * HH + t], a0);
        a1 = fmaf(wv, encb[s * HH + t + 256], a1);
    }
    g_ctxT[t * BB + b] = a0;
    g_ctxT[(t + 256) * BB + b] = a1;
}

// ---------------- gate bias init ---------------------------------------------
__global__ void k_gbias(const float* __restrict__ bih, const float* __restrict__ bhh) {
    int idx = blockIdx.x * 256 + threadIdx.x;
    if (idx < BB * GR) {
        int r = idx & (GR - 1);
        g_gates[idx] = bih[r] + bhh[r];
    }
}

// ---------------- gates GEMM: [64 x 2048] = d_in_ext[64,1324] @ Wcat^T -------
// BM=64, BN=128, BK=16, split-K x8, 256 threads, per-thread 4(m) x 8(n)
__global__ void __launch_bounds__(256) k_gates(const float* __restrict__ Wih,
                                               const float* __restrict__ Whh) {
    __shared__ float As[16][64];
    __shared__ float Bs[16][128];
    int t = threadIdx.x;
    int r0 = blockIdx.x * 128;     // grid.x = 16
    int kbase = blockIdx.y * 176;  // grid.y = 8 -> covers 1408 >= 1324
    int j = t & 15, i = t >> 4;
    int m0 = i * 4, n0 = j * 8;

    ull acc[4][4];
#pragma unroll
    for (int a = 0; a < 4; a++)
#pragma unroll
        for (int p = 0; p < 4; p++) acc[a][p] = pack2(0.f, 0.f);

    int rl = t & 127, kh = t >> 7;
    int r = r0 + rl;

    for (int k0 = kbase; k0 < kbase + 176; k0 += 16) {
        // A tile: [kk][m] from transposed scratch (xe | ctx | hprev)
#pragma unroll
        for (int q = 0; q < 4; q++) {
            int idx = t * 4 + q;
            int kk = idx >> 6, mm = idx & 63;
            int k = k0 + kk;
            float v;
            if (k >= KG) v = 0.f;
            else if (k < EE) v = g_xeT[k * BB + mm];
            else if (k < EE + HH) v = g_ctxT[(k - EE) * BB + mm];
            else v = g_hprevT[(k - EE - HH) * BB + mm];
            As[kk][mm] = v;
        }
        // B tile: row r, 8 k's per thread (piecewise Wih|Whh)
#pragma unroll
        for (int g = 0; g < 2; g++) {
            int k = k0 + kh * 8 + g * 4;
            float4 v;
            if (k + 3 < 812) {
                v = *reinterpret_cast<const float4*>(Wih + (size_t)r * 812 + k);
            } else if (k >= 812 && k + 3 < KG) {
                v = *reinterpret_cast<const float4*>(Whh + (size_t)r * 512 + (k - 812));
            } else {
                float tmp[4];
#pragma unroll
                for (int q = 0; q < 4; q++) {
                    int kq = k + q;
                    tmp[q] = (kq < 812) ? Wih[(size_t)r * 812 + kq]
                           : (kq < KG) ? Whh[(size_t)r * 512 + (kq - 812)] : 0.f;
                }
                v = make_float4(tmp[0], tmp[1], tmp[2], tmp[3]);
            }
            int kk = kh * 8 + g * 4;
            Bs[kk + 0][rl] = v.x; Bs[kk + 1][rl] = v.y;
            Bs[kk + 2][rl] = v.z; Bs[kk + 3][rl] = v.w;
        }
        __syncthreads();
#pragma unroll
        for (int kk = 0; kk < 16; kk++) {
            float4 a4 = *reinterpret_cast<const float4*>(&As[kk][m0]);
            ull ad[4] = {pack2(a4.x, a4.x), pack2(a4.y, a4.y),
                         pack2(a4.z, a4.z), pack2(a4.w, a4.w)};
            const ull* br = reinterpret_cast<const ull*>(&Bs[kk][n0]);
            ull bv[4] = {br[0], br[1], br[2], br[3]};
#pragma unroll
            for (int mm = 0; mm < 4; mm++)
#pragma unroll
                for (int p = 0; p < 4; p++) fma2(acc[mm][p], ad[mm], bv[p]);
        }
        __syncthreads();
    }
#pragma unroll
    for (int mm = 0; mm < 4; mm++) {
        int b_ = m0 + mm;
#pragma unroll
        for (int p = 0; p < 4; p++) {
            float lo, hi;
            unpack2(acc[mm][p], lo, hi);
            int rr = r0 + n0 + 2 * p;
            atomicAdd(&g_gates[b_ * GR + rr], lo);
            atomicAdd(&g_gates[b_ * GR + rr + 1], hi);
        }
    }
}

// ---------------- LSTM elementwise -------------------------------------------
__global__ void k_lstm(const float* __restrict__ c0, float* __restrict__ out) {
    int idx = blockIdx.x * 256 + threadIdx.x;  // 0..32767
    int b = idx >> 9, h = idx & (HH - 1);
    const float* g = g_gates + b * GR;
    float gi = g[h], gf = g[HH + h], gg = g[2 * HH + h], go = g[3 * HH + h];
    float c = fast_sigm(gf) * c0[idx] + fast_sigm(gi) * fast_tanh(gg);
    float hn = fast_sigm(go) * fast_tanh(c);
    out[OUT_H_OFF + idx] = hn;
    out[OUT_C_OFF + idx] = c;
    g_hnewT[h * BB + b] = hn;
}

// ---------------- p_gen: sigmoid(gen_w . [ctx, h_new, xe] + gen_b) -----------
__global__ void k_pgen(const float* __restrict__ genw, const float* __restrict__ genb) {
    int b = blockIdx.x * 8 + (threadIdx.x >> 5);
    int lane = threadIdx.x & 31;
    float p = 0.f;
    for (int k = lane; k < KG; k += 32) {
        float a;
        if (k < HH) a = g_ctxT[k * BB + b];
        else if (k < 2 * HH) a = g_hnewT[(k - HH) * BB + b];
        else a = g_xeT[(k - 2 * HH) * BB + b];
        p = fmaf(a, genw[k], p);
    }
#pragma unroll
    for (int o = 16; o; o >>= 1) p += __shfl_xor_sync(~0u, p, o);
    if (lane == 0) g_pgen[b] = fast_sigm(p + genb[0]);
}

// ---------------- output GEMM + p_gen scaling --------------------------------
// out[b,v] = p_gen[b] * (out_cat[b] . out_w[v] + out_b[v])
// BM=64, BN=128, BK=16, 128 threads, per-thread 8(m) x 8(n), f32x2 FMAs
__global__ void __launch_bounds__(128) k_outgemm(const float* __restrict__ outw,
                                                 const float* __restrict__ outb,
                                                 float* __restrict__ out) {
    __shared__ float As[16][64];
    __shared__ float Bs[16][128];
    int t = threadIdx.x;
    int nb = blockIdx.x * 128;
    int j = t & 15, i = t >> 4;
    int m0 = i * 8, n0 = j * 8;

    ull acc[8][4];
#pragma unroll
    for (int a = 0; a < 8; a++)
#pragma unroll
        for (int p = 0; p < 4; p++) acc[a][p] = pack2(0.f, 0.f);

    int vrow = nb + t;
    bool vok = vrow < VOCAB;
    const float4* wrow = reinterpret_cast<const float4*>(outw + (size_t)vrow * KOUT);

    for (int k0 = 0; k0 < KOUT; k0 += 16) {
#pragma unroll
        for (int q = 0; q < 8; q++) {
            int idx = t * 8 + q;
            int kk = idx >> 6, mm = idx & 63;
            int k = k0 + kk;
            As[kk][mm] = (k < HH) ? g_hnewT[k * BB + mm] : g_ctxT[(k - HH) * BB + mm];
        }
#pragma unroll
        for (int g = 0; g < 4; g++) {
            float4 v = vok ? wrow[(k0 >> 2) + g] : make_float4(0.f, 0.f, 0.f, 0.f);
            Bs[g * 4 + 0][t] = v.x; Bs[g * 4 + 1][t] = v.y;
            Bs[g * 4 + 2][t] = v.z; Bs[g * 4 + 3][t] = v.w;
        }
        __syncthreads();
#pragma unroll
        for (int kk = 0; kk < 16; kk++) {
            float4 a0 = *reinterpret_cast<const float4*>(&As[kk][m0]);
            float4 a1 = *reinterpret_cast<const float4*>(&As[kk][m0 + 4]);
            ull ad[8] = {pack2(a0.x, a0.x), pack2(a0.y, a0.y),
                         pack2(a0.z, a0.z), pack2(a0.w, a0.w),
                         pack2(a1.x, a1.x), pack2(a1.y, a1.y),
                         pack2(a1.z, a1.z), pack2(a1.w, a1.w)};
            const ull* br = reinterpret_cast<const ull*>(&Bs[kk][n0]);
            ull bv[4] = {br[0], br[1], br[2], br[3]};
#pragma unroll
            for (int mm = 0; mm < 8; mm++)
#pragma unroll
                for (int p = 0; p < 4; p++) fma2(acc[mm][p], ad[mm], bv[p]);
        }
        __syncthreads();
    }
#pragma unroll
    for (int mm = 0; mm < 8; mm++) {
        int b_ = m0 + mm;
        float pg = g_pgen[b_];
#pragma unroll
        for (int p = 0; p < 4; p++) {
            float lo, hi;
            unpack2(acc[mm][p], lo, hi);
            int v = nb + n0 + 2 * p;
            if (v < VOCAB)     out[(size_t)b_ * VOCAB + v]     = pg * (lo + outb[v]);
            if (v + 1 < VOCAB) out[(size_t)b_ * VOCAB + v + 1] = pg * (hi + outb[v + 1]);
        }
    }
}

// ---------------- pointer scatter (set semantics: last duplicate wins) -------
__global__ void k_scatter(const int* __restrict__ text, float* __restrict__ out) {
    __shared__ int sv[SS];
    __shared__ float sw[SS];
    int b = blockIdx.x, t = threadIdx.x;
    for (int s = t; s < SS; s += 256) {
        sv[s] = text[b * SS + s];
        sw[s] = g_attw[b * SS + s];
    }
    __syncthreads();
    float pptr = 1.f - g_pgen[b];
    for (int s = t; s < SS; s += 256) {
        int v = sv[s];
        bool last = true;
        for (int s2 = s + 1; s2 < SS; s2++)
            if (sv[s2] == v) { last = false; break; }
        if (last) out[(size_t)b * VOCAB + v] += pptr * sw[s];
    }
}

// ---------------- launch ------------------------------------------------------
extern "C" void kernel_launch(void* const* d_in, const int* in_sizes, int n_in,
                              void* d_out, int out_size) {
    // batch_size scalar may or may not be materialized as input #5
    int sh = (n_in >= 17 && in_sizes[5] == 1) ? 1 : 0;
    const int*   x    = (const int*)  d_in[0];
    const float* enc  = (const float*)d_in[1];
    const float* h0   = (const float*)d_in[2];
    const float* c0   = (const float*)d_in[3];
    const int*   text = (const int*)  d_in[4];
    const float* emb  = (const float*)d_in[5 + sh];
    const float* Vw   = (const float*)d_in[6 + sh];
    const float* Vb   = (const float*)d_in[7 + sh];
    const float* genw = (const float*)d_in[8 + sh];
    const float* genb = (const float*)d_in[9 + sh];
    const float* outw = (const float*)d_in[10 + sh];
    const float* outb = (const float*)d_in[11 + sh];
    const float* Wih  = (const float*)d_in[12 + sh];
    const float* Whh  = (const float*)d_in[13 + sh];
    const float* bih  = (const float*)d_in[14 + sh];
    const float* bhh  = (const float*)d_in[15 + sh];
    float* out = (float*)d_out;

    k_embed<<<75, 256>>>(x, emb);
    k_attn<<<64, 256>>>(enc, h0, Vw, Vb);
    k_gbias<<<512, 256>>>(bih, bhh);
    dim3 gg(16, 8);
    k_gates<<<gg, 256>>>(Wih, Whh);
    k_lstm<<<128, 256>>>(c0, out);
    k_pgen<<<8, 256>>>(genw, genb);
    k_outgemm<<<391, 128>>>(outw, outb, out);
    k_scatter<<<64, 256>>>(text, out);
}